// round 3
// baseline (speedup 1.0000x reference)
#include <cuda_runtime.h>
#include <float.h>

// Problem constants (from reference)
#define B_      8
#define L_      2048
#define D_      256
#define T_      32
#define S_PARA  8
#define S_ADU   24
#define S_SHELL 24

#define D4      (D_ / 4)          // 64 float4 lanes per row
#define ROWS_TOPIC  (B_)                  // 8
#define ROWS_PARA   (B_ * S_PARA)         // 64
#define ROWS_SHELL  (B_ * S_SHELL)        // 192
#define ROWS_ADU    (B_ * S_ADU)          // 192
#define ROWS_TOTAL  (ROWS_TOPIC + ROWS_PARA + ROWS_SHELL + ROWS_ADU)  // 456

// flat output offsets (float elements), reference return order:
// (topic_out, para_reps, span_reps<-shell, adu_reps<-x)
#define OFF_TOPIC 0
#define OFF_PARA  (B_ * D_)                              // 2048
#define OFF_SHELL (OFF_PARA + B_ * S_PARA * D_)          // 18432
#define OFF_ADU   (OFF_SHELL + B_ * S_SHELL * D_)        // 67584

#define YS 4              // span-dimension split per block
#define CHUNK 64          // rows per chunk (per block)
#define PARA_CHUNKS 4     // max para span = 256 rows -> 4 chunks

// scratch slot layout:
//   topic:  slots [0, 8)                    (1 chunk each)
//   para:   slots [8, 8+64*4)   = [8,264)   (4 chunks each)
//   shell:  slots [264, 456)                (1 chunk each)
//   adu:    slots [456, 648)                (1 chunk each)
#define SLOT_TOPIC 0
#define SLOT_PARA  (SLOT_TOPIC + ROWS_TOPIC)                 // 8
#define SLOT_SHELL (SLOT_PARA + ROWS_PARA * PARA_CHUNKS)     // 264
#define SLOT_ADU   (SLOT_SHELL + ROWS_SHELL)                 // 456
#define SLOTS_TOTAL (SLOT_ADU + ROWS_ADU)                    // 648

__device__ float g_scratch[SLOTS_TOTAL * D_];   // 664 KB static scratch

__device__ __forceinline__ float4 f4max(float4 a, float4 b) {
    float4 r;
    r.x = fmaxf(a.x, b.x);
    r.y = fmaxf(a.y, b.y);
    r.z = fmaxf(a.z, b.z);
    r.w = fmaxf(a.w, b.w);
    return r;
}

// ── Kernel A: per-chunk partial max ────────────────────────────────────────
__global__ __launch_bounds__(64 * YS) void chunk_max_kernel(
    const float* __restrict__ topic_reps,   // [B,T,D]
    const float* __restrict__ word_reps,    // [B,L,D]
    const int*   __restrict__ para_spans,   // [B,S_PARA,3]
    const int*   __restrict__ x_spans,      // [B,S_ADU,3]
    const int*   __restrict__ shell_spans)  // [B,S_SHELL,3]
{
    __shared__ float4 red[YS][D4];          // 4 KB

    const int slot = blockIdx.x;            // 0..647
    const int lane = threadIdx.x;           // 0..63
    const int ys   = threadIdx.y;           // 0..3

    const float4* src;      // first row of this chunk, at this lane
    int cnt;                // rows in this chunk (may be <=0 for empty chunks)

    if (slot < SLOT_PARA) {
        // topic row
        src = (const float4*)(topic_reps + (size_t)slot * T_ * D_) + lane;
        cnt = T_;
    } else if (slot < SLOT_SHELL) {
        const int k = slot - SLOT_PARA;
        const int i = k >> 2;               // para span index 0..63
        const int c = k & 3;                // chunk 0..3
        const int* sp = para_spans + i * 3;
        const int start = sp[1] + c * CHUNK;
        src = (const float4*)(word_reps + ((size_t)sp[0] * L_ + start) * D_) + lane;
        cnt = (sp[2] - sp[1] + 1) - c * CHUNK;
        if (cnt > CHUNK) cnt = CHUNK;
    } else if (slot < SLOT_ADU) {
        const int i = slot - SLOT_SHELL;
        const int* sp = shell_spans + i * 3;
        src = (const float4*)(word_reps + ((size_t)sp[0] * L_ + sp[1]) * D_) + lane;
        cnt = sp[2] - sp[1] + 1;
    } else {
        const int i = slot - SLOT_ADU;
        const int* sp = x_spans + i * 3;
        src = (const float4*)(word_reps + ((size_t)sp[0] * L_ + sp[1]) * D_) + lane;
        cnt = sp[2] - sp[1] + 1;
    }

    float4 acc = make_float4(-FLT_MAX, -FLT_MAX, -FLT_MAX, -FLT_MAX);

    int i = ys;
    for (; i + 3 * YS < cnt; i += 4 * YS) {
        float4 v0 = __ldg(src + (size_t)(i + 0 * YS) * D4);
        float4 v1 = __ldg(src + (size_t)(i + 1 * YS) * D4);
        float4 v2 = __ldg(src + (size_t)(i + 2 * YS) * D4);
        float4 v3 = __ldg(src + (size_t)(i + 3 * YS) * D4);
        acc = f4max(acc, f4max(f4max(v0, v1), f4max(v2, v3)));
    }
    for (; i < cnt; i += YS) {
        acc = f4max(acc, __ldg(src + (size_t)i * D4));
    }

    red[ys][lane] = acc;
    __syncthreads();

    if (ys == 0) {
        float4 r = f4max(f4max(red[0][lane], red[1][lane]),
                         f4max(red[2][lane], red[3][lane]));
        ((float4*)(g_scratch + (size_t)slot * D_))[lane] = r;
    }
}

// ── Kernel B: reduce partials -> d_out ─────────────────────────────────────
// One thread per (output row, float4 lane): 456*64 = 29184 threads.
__global__ __launch_bounds__(256) void reduce_kernel(float* __restrict__ out)
{
    const int tid  = blockIdx.x * 256 + threadIdx.x;
    const int row  = tid >> 6;              // 0..455
    const int lane = tid & 63;              // 0..63
    if (row >= ROWS_TOTAL) return;

    const float4* sc = (const float4*)g_scratch;
    float4 r;
    int out_off;

    if (row < ROWS_TOPIC) {
        r = sc[(size_t)(SLOT_TOPIC + row) * D4 + lane];
        out_off = OFF_TOPIC + row * D_;
    } else if (row < ROWS_TOPIC + ROWS_PARA) {
        const int i = row - ROWS_TOPIC;
        const size_t base = (size_t)(SLOT_PARA + i * PARA_CHUNKS) * D4 + lane;
        float4 a = sc[base + 0 * D4];
        float4 b = sc[base + 1 * D4];
        float4 c = sc[base + 2 * D4];
        float4 d = sc[base + 3 * D4];
        r = f4max(f4max(a, b), f4max(c, d));
        out_off = OFF_PARA + i * D_;
    } else if (row < ROWS_TOPIC + ROWS_PARA + ROWS_SHELL) {
        const int i = row - (ROWS_TOPIC + ROWS_PARA);
        r = sc[(size_t)(SLOT_SHELL + i) * D4 + lane];
        out_off = OFF_SHELL + i * D_;
    } else {
        const int i = row - (ROWS_TOPIC + ROWS_PARA + ROWS_SHELL);
        r = sc[(size_t)(SLOT_ADU + i) * D4 + lane];
        out_off = OFF_ADU + i * D_;
    }

    ((float4*)(out + out_off))[lane] = r;
}

extern "C" void kernel_launch(void* const* d_in, const int* in_sizes, int n_in,
                              void* d_out, int out_size) {
    // metadata order: topic_reps, word_reps, topic_lens(int64, unused),
    //                 para_spans, x_spans, shell_spans
    const float* topic_reps  = (const float*)d_in[0];
    const float* word_reps   = (const float*)d_in[1];
    const int*   para_spans  = (const int*)d_in[3];
    const int*   x_spans     = (const int*)d_in[4];
    const int*   shell_spans = (const int*)d_in[5];
    float* out = (float*)d_out;

    dim3 blockA(64, YS);
    chunk_max_kernel<<<SLOTS_TOTAL, blockA>>>(topic_reps, word_reps,
                                              para_spans, x_spans, shell_spans);

    const int threadsB = ROWS_TOTAL * D4;             // 29184
    reduce_kernel<<<(threadsB + 255) / 256, 256>>>(out);
}